// round 8
// baseline (speedup 1.0000x reference)
#include <cuda_runtime.h>
#include <cstdint>

#define D 512
#define HW (D * D)            // 262144 = 2^18
#define NB 32                 // batch
#define IMG_ELEMS ((size_t)NB * 3 * HW)
#define LO 0.001f
#define HI 510.999f           // D - 1.001
#define NBLOCKS 8192          // 16*16 tiles * 32 batch

#define HALO 6
#define WIN  44               // 32 + 2*HALO
#define WPAD 45                // padded row stride (floats)

__device__ __align__(16) float g_partials[NBLOCKS];

// Global-memory bilinear tap (fallback + shared math helper semantics).
__device__ __forceinline__ void sample_global(const float* __restrict__ img,
                                              int i00, int i10, int i01, int i11,
                                              float wff, float wcf, float wfc, float wcc,
                                              float r[3]) {
#pragma unroll
    for (int c = 0; c < 3; c++) {
        const float* ic = img + (size_t)c * HW;
        r[c] += wff * __ldg(ic + i00)
              + wcf * __ldg(ic + i10)
              + wfc * __ldg(ic + i01)
              + wcc * __ldg(ic + i11);
    }
}

// One branch, one pixel: taps from smem tile when in-window, global fallback otherwise.
__device__ __forceinline__ void sample_tile(const float S[3][WIN][WPAD],
                                            const float* __restrict__ gimg,
                                            int tx, int ty,
                                            float qx0, float qy0, float m,
                                            float r[3], float& loss) {
    float qx = fminf(fmaxf(qx0, LO), HI);
    float qy = fminf(fmaxf(qy0, LO), HI);
    float dx = qx0 - qx;
    float dy = qy0 - qy;
    loss += dx * dx + dy * dy;

    float fx = floorf(qx);
    float fy = floorf(qy);
    float ax = qx - fx;              // in [0,1)
    float ay = qy - fy;

    int ifx = (int)fx, ify = (int)fy;
    int icx = ifx + (ax > 0.0f);     // == (int)ceilf(qx)
    int icy = ify + (ay > 0.0f);

    float wfx = 1.0f - ax;
    float wcx = 1.0f - ((float)icx - qx);
    float wfy = 1.0f - ay;
    float wcy = 1.0f - ((float)icy - qy);

    float wff = m * (wfx * wfy);
    float wcf = m * (wcx * wfy);
    float wfc = m * (wfx * wcy);
    float wcc = m * (wcx * wcy);

    int sfx = ifx - tx + HALO;       // smem row of floor-x
    int sfy = ify - ty + HALO;       // smem col of floor-y
    int scx = icx - tx + HALO;
    int scy = icy - ty + HALO;

    bool in = (sfx >= 0) & (scx < WIN) & (sfy >= 0) & (scy < WIN);
    if (__builtin_expect(in, 1)) {
#pragma unroll
        for (int c = 0; c < 3; c++) {
            r[c] += wff * S[c][sfx][sfy]
                  + wcf * S[c][scx][sfy]
                  + wfc * S[c][sfx][scy]
                  + wcc * S[c][scx][scy];
        }
    } else {
        int i00 = ify + (ifx << 9);
        int i10 = ify + (icx << 9);
        int i01 = icy + (ifx << 9);
        int i11 = icy + (icx << 9);
        sample_global(gimg, i00, i10, i01, i11, wff, wcf, wfc, wcc, r);
    }
}

// Stage a clamped 44x44 halo window (3 channels) into smem. Coalesced LDG -> STS.
__device__ __forceinline__ void stage_tile(float S[3][WIN][WPAD],
                                           const float* __restrict__ img,
                                           int tx, int ty) {
    for (int idx = threadIdx.x; idx < 3 * WIN * WIN; idx += 256) {
        int c   = idx / (WIN * WIN);
        int rem = idx - c * (WIN * WIN);
        int rr  = rem / WIN;
        int cc  = rem - rr * WIN;
        int xr = min(max(tx - HALO + rr, 0), D - 1);
        int yc = min(max(ty - HALO + cc, 0), D - 1);
        S[c][rr][cc] = __ldg(img + (size_t)c * HW + (xr << 9) + yc);
    }
}

// Block = 32x32 pixel tile of one batch image.
//   lane (0..31) -> y within tile; warp (0..7) -> 4 consecutive rows via ILP.
// Two passes over one smem buffer: branch a (im1), then branch b (im2).
__global__ void __launch_bounds__(256) vm_main_kernel(
    const float* __restrict__ im1,
    const float* __restrict__ im2,
    const float* __restrict__ C,
    const float* __restrict__ M1,
    const float* __restrict__ M2,
    float* __restrict__ out) {

    __shared__ float S[3][WIN][WPAD];      // 23.76 KB
    __shared__ float warp_part[8];

    int bid = blockIdx.x;
    int ty = (bid & 15) << 5;           // tile y origin
    int tx = ((bid >> 4) & 15) << 5;    // tile x origin
    int n  = bid >> 8;                  // batch

    int lane = threadIdx.x & 31;
    int w    = threadIdx.x >> 5;

    int y  = ty + lane;                 // column, fixed per thread
    int x0 = tx + (w << 2);             // first of 4 rows

    const float* Cn  = C  + (size_t)n * 2 * HW;
    const float* M1n = M1 + (size_t)n * HW;
    const float* M2n = M2 + (size_t)n * HW;
    const float* im1n = im1 + (size_t)n * 3 * HW;
    const float* im2n = im2 + (size_t)n * 3 * HW;
    float* outn = out + (size_t)n * 3 * HW;

    float yf = (float)y;
    float loss = 0.0f;

    float r[12];
#pragma unroll
    for (int i = 0; i < 12; i++) r[i] = 0.0f;

    // ---- pass A: branch a = im1 sampled at q + C, masked by M1 ----
    stage_tile(S, im1n, tx, ty);
    __syncthreads();
#pragma unroll
    for (int i = 0; i < 4; i++) {
        int x = x0 + i;
        int p = (x << 9) + y;
        float xf = (float)x;
        float c0 = __ldg(Cn + p);
        float c1 = __ldg(Cn + p + HW);
        float m1 = __ldg(M1n + p);
        sample_tile(S, im1n, tx, ty, xf + c0, yf + c1, m1, &r[i * 3], loss);
    }
    __syncthreads();

    // ---- pass B: branch b = im2 sampled at q - C, masked by M2 ----
    stage_tile(S, im2n, tx, ty);
    __syncthreads();
#pragma unroll
    for (int i = 0; i < 4; i++) {
        int x = x0 + i;
        int p = (x << 9) + y;
        float xf = (float)x;
        float c0 = __ldg(Cn + p);
        float c1 = __ldg(Cn + p + HW);
        float m2 = __ldg(M2n + p);
        sample_tile(S, im2n, tx, ty, xf - c0, yf - c1, m2, &r[i * 3], loss);

        // store this row: 3 warp-coalesced 128B stores
        outn[p]          = r[i * 3 + 0];
        outn[p + HW]     = r[i * 3 + 1];
        outn[p + 2 * HW] = r[i * 3 + 2];
    }

    // ---- loss reduction: warp shfl -> smem -> per-block partial ----
#pragma unroll
    for (int off = 16; off > 0; off >>= 1)
        loss += __shfl_down_sync(0xFFFFFFFFu, loss, off);

    if (lane == 0) warp_part[w] = loss;
    __syncthreads();
    if (threadIdx.x == 0) {
        float v = warp_part[0];
#pragma unroll
        for (int k = 1; k < 8; k++) v += warp_part[k];
        g_partials[bid] = v;
    }
}

__global__ void __launch_bounds__(1024) vm_finalize_kernel(float* __restrict__ out) {
    int t = threadIdx.x;
    const float4* p4 = (const float4*)g_partials;   // 2048 float4s
    float s = 0.0f;
#pragma unroll
    for (int i = 0; i < 2; i++) {
        float4 v = p4[t + i * 1024];
        s += (v.x + v.y) + (v.z + v.w);
    }
#pragma unroll
    for (int off = 16; off > 0; off >>= 1)
        s += __shfl_down_sync(0xFFFFFFFFu, s, off);
    __shared__ float warp_part[32];
    int w = t >> 5, lane = t & 31;
    if (lane == 0) warp_part[w] = s;
    __syncthreads();
    if (w == 0) {
        float v = warp_part[lane];
#pragma unroll
        for (int off = 16; off > 0; off >>= 1)
            v += __shfl_down_sync(0xFFFFFFFFu, v, off);
        if (lane == 0) {
            // la + lb = sum / (N*2*HW) / (D*D) * 0.01
            double denom = (double)NB * 2.0 * (double)HW;
            out[IMG_ELEMS] = (float)((double)v / denom * (0.01 / (double)(D * D)));
        }
    }
}

extern "C" void kernel_launch(void* const* d_in, const int* in_sizes, int n_in,
                              void* d_out, int out_size) {
    const float* im1 = (const float*)d_in[0];
    const float* im2 = (const float*)d_in[1];
    const float* C   = (const float*)d_in[2];
    const float* M1  = (const float*)d_in[3];
    const float* M2  = (const float*)d_in[4];
    float* out = (float*)d_out;

    vm_main_kernel<<<NBLOCKS, 256>>>(im1, im2, C, M1, M2, out);

    if ((size_t)out_size > IMG_ELEMS) {
        vm_finalize_kernel<<<1, 1024>>>(out);
    }
}

// round 9
// speedup vs baseline: 1.7324x; 1.7324x over previous
#include <cuda_runtime.h>
#include <cstdint>

#define D 512
#define HW (D * D)            // 262144 = 2^18
#define NB 32                 // batch
#define IMG_ELEMS ((size_t)NB * 3 * HW)
#define LO 0.001f
#define HI 510.999f           // D - 1.001
#define NPBLOCKS 740          // 148 SMs * 5 resident blocks (48-reg budget)
#define NITEMS 32768          // 32 batch * 64 x-tiles(8 rows) * 16 y-tiles(32 cols)

__device__ __align__(16) float g_partials[NPBLOCKS];

// One branch, one pixel. img points at batch-n's [3,HW] plane set.
__device__ __forceinline__ void sample_branch(const float* __restrict__ img,
                                              float qx0, float qy0, float m,
                                              float r[3],
                                              float& loss) {
    float qx = fminf(fmaxf(qx0, LO), HI);
    float qy = fminf(fmaxf(qy0, LO), HI);
    float dx = qx0 - qx;
    float dy = qy0 - qy;
    loss += dx * dx + dy * dy;

    float fx = floorf(qx);
    float fy = floorf(qy);
    float ax = qx - fx;              // in [0,1)
    float ay = qy - fy;

    int ifx = (int)fx, ify = (int)fy;
    int icx = ifx + (ax > 0.0f);     // == (int)ceilf(qx)
    int icy = ify + (ay > 0.0f);

    // weights: 1 - |q - nb|
    float wfx = 1.0f - ax;
    float wcx = 1.0f - ((float)icx - qx);
    float wfy = 1.0f - ay;
    float wcy = 1.0f - ((float)icy - qy);

    // ind = y + D * x
    int i00 = ify + (ifx << 9);
    int i10 = ify + (icx << 9);
    int i01 = icy + (ifx << 9);
    int i11 = icy + (icx << 9);

    float wff = m * (wfx * wfy);
    float wcf = m * (wcx * wfy);
    float wfc = m * (wfx * wcy);
    float wcc = m * (wcx * wcy);

#pragma unroll
    for (int c = 0; c < 3; c++) {
        const float* ic = img + (size_t)c * HW;
        r[c] += wff * __ldg(ic + i00)
              + wcf * __ldg(ic + i10)
              + wfc * __ldg(ic + i01)
              + wcc * __ldg(ic + i11);
    }
}

// Persistent kernel: 740 blocks stride over 32768 items.
// Item = 8-row x 32-col tile of one batch image.
//   lane (0..31) -> y (one cache-line column), warp (0..7) -> row within tile.
__global__ void __launch_bounds__(256) vm_main_kernel(
    const float* __restrict__ im1,
    const float* __restrict__ im2,
    const float* __restrict__ C,
    const float* __restrict__ M1,
    const float* __restrict__ M2,
    float* __restrict__ out) {

    int lane = threadIdx.x & 31;
    int w    = threadIdx.x >> 5;

    float loss = 0.0f;

    for (int item = blockIdx.x; item < NITEMS; item += NPBLOCKS) {
        int n  = item >> 10;            // 1024 items per image
        int xt = (item >> 4) & 63;      // 64 x-tiles of 8 rows
        int yt = item & 15;             // 16 y-tiles of 32 cols

        int x = (xt << 3) + w;          // row (one per warp)
        int y = (yt << 5) + lane;       // column (one per lane)
        int p = (x << 9) + y;

        const float* Cn  = C  + (size_t)n * 2 * HW;
        float c0 = __ldg(Cn + p);            // row-flow
        float c1 = __ldg(Cn + p + HW);       // col-flow
        float m1 = __ldg(M1 + (size_t)n * HW + p);
        float m2 = __ldg(M2 + (size_t)n * HW + p);

        float xf = (float)x;
        float yf = (float)y;

        float r[3] = {0.0f, 0.0f, 0.0f};
        const float* im1n = im1 + (size_t)n * 3 * HW;
        const float* im2n = im2 + (size_t)n * 3 * HW;

        // branch a: im1 sampled at q + C, masked by M1
        sample_branch(im1n, xf + c0, yf + c1, m1, r, loss);
        // branch b: im2 sampled at q - C, masked by M2
        sample_branch(im2n, xf - c0, yf - c1, m2, r, loss);

        float* outn = out + (size_t)n * 3 * HW;
        outn[p]          = r[0];
        outn[p + HW]     = r[1];
        outn[p + 2 * HW] = r[2];
    }

    // ---- loss reduction: warp shfl -> smem -> per-block partial ----
#pragma unroll
    for (int off = 16; off > 0; off >>= 1)
        loss += __shfl_down_sync(0xFFFFFFFFu, loss, off);

    __shared__ float warp_part[8];
    if (lane == 0) warp_part[w] = loss;
    __syncthreads();
    if (threadIdx.x == 0) {
        float v = warp_part[0];
#pragma unroll
        for (int k = 1; k < 8; k++) v += warp_part[k];
        g_partials[blockIdx.x] = v;
    }
}

__global__ void __launch_bounds__(256) vm_finalize_kernel(float* __restrict__ out) {
    int t = threadIdx.x;
    float s = 0.0f;
    for (int i = t; i < NPBLOCKS; i += 256)
        s += g_partials[i];
#pragma unroll
    for (int off = 16; off > 0; off >>= 1)
        s += __shfl_down_sync(0xFFFFFFFFu, s, off);
    __shared__ float warp_part[8];
    int w = t >> 5, lane = t & 31;
    if (lane == 0) warp_part[w] = s;
    __syncthreads();
    if (t == 0) {
        float v = warp_part[0];
#pragma unroll
        for (int k = 1; k < 8; k++) v += warp_part[k];
        // la + lb = sum / (N*2*HW) / (D*D) * 0.01
        double denom = (double)NB * 2.0 * (double)HW;
        out[IMG_ELEMS] = (float)((double)v / denom * (0.01 / (double)(D * D)));
    }
}

extern "C" void kernel_launch(void* const* d_in, const int* in_sizes, int n_in,
                              void* d_out, int out_size) {
    const float* im1 = (const float*)d_in[0];
    const float* im2 = (const float*)d_in[1];
    const float* C   = (const float*)d_in[2];
    const float* M1  = (const float*)d_in[3];
    const float* M2  = (const float*)d_in[4];
    float* out = (float*)d_out;

    vm_main_kernel<<<NPBLOCKS, 256>>>(im1, im2, C, M1, M2, out);

    if ((size_t)out_size > IMG_ELEMS) {
        vm_finalize_kernel<<<1, 256>>>(out);
    }
}